// round 16
// baseline (speedup 1.0000x reference)
#include <cuda_runtime.h>
#include <cuda_fp16.h>
#include <cstdint>

#define NN 8192
#define FI 128
#define FO 64
#define LRALPHA 0.2f
#define KSPLIT 4
#define MT 128          // M rows per CTA
#define KT 64           // j per K-tile
#define NBF 64          // B rows
#define STRIDE_OUT 72

// ---------------- device scratch ----------------
__device__ __align__(16) float g_t[NN];
__device__ __align__(16) float g_u[NN], g_v[NN];   // fp32 exp(t), exp(a t)
__device__ float g_s[NN];
__device__ unsigned g_Tkey = 0;                    // monotonic-encoded max_j t_j
__device__ __align__(16) __half g_Bh[(size_t)NBF*NN];  // fp16 RN of h, N-major
__device__ float g_num[KSPLIT][(size_t)NN*STRIDE_OUT];

// ---------------- helpers ----------------
__device__ __forceinline__ uint32_t smem_u32(const void* p) {
    uint32_t a;
    asm("{ .reg .u64 t; cvta.to.shared.u64 t, %1; cvt.u32.u64 %0, t; }" : "=r"(a) : "l"(p));
    return a;
}
#define SWZ(x) ((uint32_t)(x) ^ ((((uint32_t)(x)) >> 3) & 0x70u))

// order-preserving float->uint key (works for all signs)
__device__ __forceinline__ unsigned fkey(float f) {
    unsigned u = __float_as_uint(f);
    return u ^ (((int)u >> 31) | 0x80000000u);
}
__device__ __forceinline__ float funkey(unsigned k) {
    unsigned u = k ^ ((~(int)k >> 31) | 0x80000000u);
    return __uint_as_float(u);
}

__device__ __forceinline__ void ldm_x4(uint32_t addr, uint32_t r[4]) {
    asm volatile("ldmatrix.sync.aligned.m8n8.x4.shared.b16 {%0,%1,%2,%3}, [%4];"
        : "=r"(r[0]), "=r"(r[1]), "=r"(r[2]), "=r"(r[3]) : "r"(addr));
}
__device__ __forceinline__ void mma16816(float* c, const uint32_t* a, const uint32_t* b) {
    asm("mma.sync.aligned.m16n8k16.row.col.f32.f16.f16.f32 "
        "{%0,%1,%2,%3}, {%4,%5,%6,%7}, {%8,%9}, {%0,%1,%2,%3};"
        : "+f"(c[0]), "+f"(c[1]), "+f"(c[2]), "+f"(c[3])
        : "r"(a[0]), "r"(a[1]), "r"(a[2]), "r"(a[3]), "r"(b[0]), "r"(b[1]));
}
__device__ __forceinline__ void cp16(uint32_t dst, const void* src) {
    asm volatile("cp.async.cg.shared.global [%0], [%1], 16;" :: "r"(dst), "l"(src) : "memory");
}
#define CP_COMMIT() asm volatile("cp.async.commit_group;" ::: "memory")
#define CP_WAIT(n)  asm volatile("cp.async.wait_group %0;" :: "n"(n) : "memory")
__device__ __forceinline__ void prefetchL1(const void* p) {
    asm volatile("prefetch.global.L1 [%0];" :: "l"(p));
}
// pack two fp32 into half2 (RN); also return exact fp32 sum of rounded pair
__device__ __forceinline__ uint32_t pack_rn(float a, float b, float& sum) {
    __half2 t = __floats2half2_rn(a, b);
    float2 f = __half22float2(t);
    sum = f.x + f.y;
    return *reinterpret_cast<uint32_t*>(&t);
}

// ---- kernel 1: h = x @ W (32 rows/CTA), scalars + fp16 table + T atomicMax ----
__global__ void k_gemm_h(const float* __restrict__ x, const float* __restrict__ W,
                         const float* __restrict__ a) {
    __shared__ float sW[FI*FO];       // 32KB; reused as sh[32][65]
    __shared__ float sx[32][132];     // padded
    int tid = threadIdx.x;
    for (int i = tid; i < FI*FO; i += 256) sW[i] = W[i];
    int r0 = blockIdx.x * 32;
    for (int i = tid; i < 32*FI; i += 256)
        sx[i >> 7][i & 127] = x[(size_t)(r0 + (i >> 7))*FI + (i & 127)];
    __syncthreads();
    int c4 = (tid & 15) * 4;
    int r2 = (tid >> 4) * 2;
    float acc4[2][4];
    #pragma unroll
    for (int i = 0; i < 2; i++)
        #pragma unroll
        for (int j = 0; j < 4; j++) acc4[i][j] = 0.f;
    #pragma unroll 4
    for (int k = 0; k < FI; k += 4) {
        float4 xv[2], wv[4];
        #pragma unroll
        for (int i = 0; i < 2; i++) xv[i] = *(const float4*)&sx[r2 + i][k];
        #pragma unroll
        for (int j = 0; j < 4; j++) wv[j] = *(const float4*)&sW[(k + j)*FO + c4];
        #pragma unroll
        for (int i = 0; i < 2; i++) {
            acc4[i][0] += xv[i].x*wv[0].x + xv[i].y*wv[1].x + xv[i].z*wv[2].x + xv[i].w*wv[3].x;
            acc4[i][1] += xv[i].x*wv[0].y + xv[i].y*wv[1].y + xv[i].z*wv[2].y + xv[i].w*wv[3].y;
            acc4[i][2] += xv[i].x*wv[0].z + xv[i].y*wv[1].z + xv[i].z*wv[2].z + xv[i].w*wv[3].z;
            acc4[i][3] += xv[i].x*wv[0].w + xv[i].y*wv[1].w + xv[i].z*wv[2].w + xv[i].w*wv[3].w;
        }
    }
    __syncthreads();    // all sW reads done; reuse as padded sh[32][65]
    float* sh = sW;
    #pragma unroll
    for (int i = 0; i < 2; i++)
        #pragma unroll
        for (int j = 0; j < 4; j++)
            sh[(r2 + i)*65 + c4 + j] = acc4[i][j];
    __syncthreads();
    int w = tid >> 5, lane = tid & 31;
    float tmax = -1e30f;
    #pragma unroll
    for (int rr = w * 4; rr < w * 4 + 4; rr++) {
        float h0 = sh[rr*65 + lane];
        float h1 = sh[rr*65 + 32 + lane];
        float s = h0 * a[lane]      + h1 * a[lane + 32];
        float t = h0 * a[lane + 64] + h1 * a[lane + 96];
        #pragma unroll
        for (int o = 16; o; o >>= 1) {
            s += __shfl_xor_sync(0xffffffffu, s, o);
            t += __shfl_xor_sync(0xffffffffu, t, o);
        }
        tmax = fmaxf(tmax, t);
        if (lane == 0) {
            int gi = r0 + rr;
            g_s[gi] = s; g_t[gi] = t;
            g_u[gi] = expf(t); g_v[gi] = expf(LRALPHA * t);
        }
    }
    if (lane == 0) atomicMax(&g_Tkey, fkey(tmax));
    // N-major fp16 RN table for this 32-row j-slice
    {
        int jj = tid & 31;
        for (int n = tid >> 5; n < FO; n += 8)
            g_Bh[(size_t)n*NN + r0 + jj] = __float2half_rn(sh[jj*65 + n]);
    }
}

// ---------------- kernel 2: single-stream pipelined fp16 HMMA masked GEMM ----------------
// SMEM: s/p/q 2K | W 2 stages x 16K | B 2 stages x 8K = 51200 (x3 CTAs = 150K)
#define SM_SS    0
#define SM_W     2048
#define A_BYTES  (MT*128)                    // 16384
#define W_STG    A_BYTES
#define SM_B     (SM_W + 2*W_STG)            // 34816
#define B_BYTES  (NBF*128)                   // 8192
#define BSTG     B_BYTES
#define SM_TOTAL (SM_B + 2*BSTG)             // 51200

__global__ void __launch_bounds__(256, 3) k_main_tc(const int* __restrict__ adj) {
    extern __shared__ char smem[];
    uint32_t sb = smem_u32(smem);
    int tid = threadIdx.x, w = tid >> 5, lane = tid & 31;
    int wm = w & 3, wn = w >> 2;                 // 4 M-groups x 2 N-groups
    int i0 = blockIdx.x * MT;
    int sp = blockIdx.y;
    int jbase = sp * (NN / KSPLIT);
    const int nTiles = (NN / KSPLIT) / KT;       // 32

    float* s_s = (float*)(smem + SM_SS);         // [128]
    float* s_p = s_s + 128;
    float* s_q = s_s + 256;
    if (tid < MT) {
        float s = g_s[i0 + tid];
        float T = funkey(g_Tkey);
        float e = s + T;
        float mi = e > 0.f ? e : LRALPHA * e;    // = max_j leakyrelu(s+t_j)
        s_s[tid] = s;
        s_p[tid] = expf(s - mi);
        s_q[tid] = expf(LRALPHA * s - mi);
    }

    float acc[2][4][4];
    #pragma unroll
    for (int mt = 0; mt < 2; mt++)
        #pragma unroll
        for (int nb = 0; nb < 4; nb++)
            #pragma unroll
            for (int e = 0; e < 4; e++) acc[mt][nb][e] = 0.f;
    float rsum[4] = {0.f, 0.f, 0.f, 0.f};

    int nbBase = wn * 4;
    uint32_t aRowByte = (uint32_t)(wm * 32 + (lane & 15)) * 128;
    uint32_t aKHalf   = ((lane >> 4) & 1) * 16;
    uint32_t bByte    = (uint32_t)(lane & 7) * 128 + ((lane >> 3) & 1) * 16
                      + ((lane >> 4) & 1) * 1024;

    // build-phase fixed coordinates
    int seg   = tid & 7;          // j segment of 8
    int rbase = tid >> 3;         // 0..31; row = it*32 + rbase

    auto prefetchB = [&](int tt, int st) {
        int j0 = jbase + tt * KT;
        uint32_t bdst = sb + SM_B + st * BSTG;
        for (int v = tid; v < NBF * 8; v += 256) {
            int n = v >> 3, ch = v & 7;
            cp16(bdst + SWZ((uint32_t)(n * 128 + ch * 16)),
                 g_Bh + (size_t)n * NN + j0 + ch * 8);
        }
    };

    // build W(tt) fp16-RN tile into stage st; rsum over the ROUNDED values
    auto buildW = [&](int tt, int st) {
        int jc = jbase + tt * KT + seg * 8;
        char* wb = smem + SM_W + st * W_STG;
        float4 t0 = *(const float4*)(g_t + jc);
        float4 t1 = *(const float4*)(g_t + jc + 4);
        float4 u0 = *(const float4*)(g_u + jc);
        float4 u1 = *(const float4*)(g_u + jc + 4);
        float4 v0 = *(const float4*)(g_v + jc);
        float4 v1 = *(const float4*)(g_v + jc + 4);
        #pragma unroll
        for (int it = 0; it < 4; it++) {
            int r = it * 32 + rbase;
            const int* ap = adj + (size_t)(i0 + r) * NN + jc;
            int4 a0 = __ldg((const int4*)ap);
            int4 a1 = __ldg((const int4*)(ap + 4));
            float sr = s_s[r], pr_ = s_p[r], qr_ = s_q[r];
            float w0 = (a0.x > 0) ? ((sr + t0.x > 0.f) ? pr_ * u0.x : qr_ * v0.x) : 0.f;
            float w1 = (a0.y > 0) ? ((sr + t0.y > 0.f) ? pr_ * u0.y : qr_ * v0.y) : 0.f;
            float w2 = (a0.z > 0) ? ((sr + t0.z > 0.f) ? pr_ * u0.z : qr_ * v0.z) : 0.f;
            float w3 = (a0.w > 0) ? ((sr + t0.w > 0.f) ? pr_ * u0.w : qr_ * v0.w) : 0.f;
            float w4 = (a1.x > 0) ? ((sr + t1.x > 0.f) ? pr_ * u1.x : qr_ * v1.x) : 0.f;
            float w5 = (a1.y > 0) ? ((sr + t1.y > 0.f) ? pr_ * u1.y : qr_ * v1.y) : 0.f;
            float w6 = (a1.z > 0) ? ((sr + t1.z > 0.f) ? pr_ * u1.z : qr_ * v1.z) : 0.f;
            float w7 = (a1.w > 0) ? ((sr + t1.w > 0.f) ? pr_ * u1.w : qr_ * v1.w) : 0.f;
            uint4 H;
            float s0, s1, s2, s3;
            H.x = pack_rn(w0, w1, s0);
            H.y = pack_rn(w2, w3, s1);
            H.z = pack_rn(w4, w5, s2);
            H.w = pack_rn(w6, w7, s3);
            rsum[it] += (s0 + s1) + (s2 + s3);
            *(uint4*)(wb + SWZ((uint32_t)(r * 128 + seg * 16))) = H;
        }
    };

    prefetchB(0, 0);
    CP_COMMIT();
    __syncthreads();           // s_s/p/q visible
    buildW(0, 0);
    __syncthreads();           // W(0) visible to all warps

    for (int t = 0; t < nTiles; t++) {
        int st = t & 1;

        if (t + 1 < nTiles) {
            prefetchB(t + 1, 1 - st);
            CP_COMMIT();
            buildW(t + 1, 1 - st);
            CP_WAIT(1);        // B(t) complete (B(t+1) still in flight)
        } else {
            CP_WAIT(0);
        }

        if (t + 2 < nTiles)
            prefetchL1(adj + (size_t)(i0 + (tid >> 1)) * NN
                       + (jbase + (t + 2) * KT) + (tid & 1) * 32);

        // ---- MMA(t): 4 ksteps, single-buffered fragments (TLP hides latency) ----
        uint32_t wbase = sb + SM_W + st * W_STG;
        uint32_t bbase = sb + SM_B + st * BSTG;
        #pragma unroll
        for (int ks = 0; ks < 4; ks++) {
            uint32_t kB = (uint32_t)ks * 32;
            uint32_t bh[2][4], aH[2][4];
            #pragma unroll
            for (int pr = 0; pr < 2; pr++)
                ldm_x4(bbase + SWZ(bByte + (nbBase + 2 * pr) * 1024u + kB), bh[pr]);
            #pragma unroll
            for (int mt = 0; mt < 2; mt++)
                ldm_x4(wbase + SWZ(aRowByte + mt * 2048u + kB + aKHalf), aH[mt]);
            #pragma unroll
            for (int pr = 0; pr < 2; pr++) {
                mma16816(acc[0][2*pr],   aH[0], bh[pr]);
                mma16816(acc[1][2*pr],   aH[1], bh[pr]);
                mma16816(acc[0][2*pr+1], aH[0], bh[pr] + 2);
                mma16816(acc[1][2*pr+1], aH[1], bh[pr] + 2);
            }
        }
        __syncthreads();       // all warps done reading W(st), B(st)
    }

    // ---- epilogue: fp32 partials; den via deferred 8-lane reduction ----
    #pragma unroll
    for (int it = 0; it < 4; it++) {
        float rv = rsum[it];
        rv += __shfl_xor_sync(0xffffffffu, rv, 1);
        rv += __shfl_xor_sync(0xffffffffu, rv, 2);
        rv += __shfl_xor_sync(0xffffffffu, rv, 4);
        if (seg == 0)
            g_num[sp][(size_t)(i0 + it * 32 + rbase) * STRIDE_OUT + 64] = rv;
    }
    int gp = lane >> 2, tg = lane & 3;
    #pragma unroll
    for (int mt = 0; mt < 2; mt++) {
        int row0 = i0 + wm * 32 + mt * 16 + gp;
        #pragma unroll
        for (int nb = 0; nb < 4; nb++) {
            int col = (nbBase + nb) * 8 + tg * 2;
            size_t o0 = (size_t)row0 * STRIDE_OUT + col;
            size_t o1 = (size_t)(row0 + 8) * STRIDE_OUT + col;
            g_num[sp][o0]     = acc[mt][nb][0];
            g_num[sp][o0 + 1] = acc[mt][nb][1];
            g_num[sp][o1]     = acc[mt][nb][2];
            g_num[sp][o1 + 1] = acc[mt][nb][3];
        }
    }
}

// ---------------- kernel 3: combine splits, divide, ELU ----------------
__global__ void k_final(float* __restrict__ out) {
    int idx = blockIdx.x * 256 + threadIdx.x;
    int i = idx >> 6, c = idx & 63;
    size_t b = (size_t)i * STRIDE_OUT;
    float num = 0.f, den = 0.f;
    #pragma unroll
    for (int s2 = 0; s2 < KSPLIT; s2++) {
        num += g_num[s2][b + c];
        den += g_num[s2][b + 64];
    }
    float hv = num / den;
    out[idx] = hv > 0.f ? hv : expm1f(hv);
}

extern "C" void kernel_launch(void* const* d_in, const int* in_sizes, int n_in,
                              void* d_out, int out_size) {
    const float* x   = (const float*)d_in[0];
    const int*   adj = (const int*)  d_in[1];
    const float* W   = (const float*)d_in[2];
    const float* a   = (const float*)d_in[3];
    float* out = (float*)d_out;

    cudaFuncSetAttribute(k_main_tc, cudaFuncAttributeMaxDynamicSharedMemorySize, SM_TOTAL);

    k_gemm_h<<<NN/32, 256>>>(x, W, a);
    dim3 gm(NN/MT, KSPLIT);
    k_main_tc<<<gm, 256, SM_TOTAL>>>(adj);
    k_final<<<(NN*FO)/256, 256>>>(out);
}

// round 17
// speedup vs baseline: 1.3812x; 1.3812x over previous
#include <cuda_runtime.h>
#include <cuda_fp16.h>
#include <cstdint>

#define NN 8192
#define FI 128
#define FO 64
#define LRALPHA 0.2f
#define KSPLIT 4
#define MT 128          // M rows per CTA
#define KT 64           // j per K-tile
#define NBF 64          // B rows
#define STRIDE_OUT 72

// ---------------- device scratch ----------------
__device__ __align__(16) float g_t[NN];
__device__ __align__(16) float g_u[NN], g_v[NN];   // fp32 exp(t), exp(a t)
__device__ float g_s[NN];
__device__ unsigned g_Tkey = 0;                    // monotonic-encoded max_j t_j
__device__ __align__(16) __half g_Bh[(size_t)NBF*NN];  // fp16 RN of h, N-major
__device__ float g_num[KSPLIT][(size_t)NN*STRIDE_OUT];

// ---------------- helpers ----------------
__device__ __forceinline__ uint32_t smem_u32(const void* p) {
    uint32_t a;
    asm("{ .reg .u64 t; cvta.to.shared.u64 t, %1; cvt.u32.u64 %0, t; }" : "=r"(a) : "l"(p));
    return a;
}
#define SWZ(x) ((uint32_t)(x) ^ ((((uint32_t)(x)) >> 3) & 0x70u))

// order-preserving float->uint key
__device__ __forceinline__ unsigned fkey(float f) {
    unsigned u = __float_as_uint(f);
    return u ^ (((int)u >> 31) | 0x80000000u);
}
__device__ __forceinline__ float funkey(unsigned k) {
    unsigned u = k ^ ((~(int)k >> 31) | 0x80000000u);
    return __uint_as_float(u);
}

__device__ __forceinline__ void ldm_x4(uint32_t addr, uint32_t r[4]) {
    asm volatile("ldmatrix.sync.aligned.m8n8.x4.shared.b16 {%0,%1,%2,%3}, [%4];"
        : "=r"(r[0]), "=r"(r[1]), "=r"(r[2]), "=r"(r[3]) : "r"(addr));
}
__device__ __forceinline__ void mma16816(float* c, const uint32_t* a, const uint32_t* b) {
    asm("mma.sync.aligned.m16n8k16.row.col.f32.f16.f16.f32 "
        "{%0,%1,%2,%3}, {%4,%5,%6,%7}, {%8,%9}, {%0,%1,%2,%3};"
        : "+f"(c[0]), "+f"(c[1]), "+f"(c[2]), "+f"(c[3])
        : "r"(a[0]), "r"(a[1]), "r"(a[2]), "r"(a[3]), "r"(b[0]), "r"(b[1]));
}
__device__ __forceinline__ void cp16(uint32_t dst, const void* src) {
    asm volatile("cp.async.cg.shared.global [%0], [%1], 16;" :: "r"(dst), "l"(src) : "memory");
}
#define CP_COMMIT() asm volatile("cp.async.commit_group;" ::: "memory")
#define CP_WAIT(n)  asm volatile("cp.async.wait_group %0;" :: "n"(n) : "memory")
__device__ __forceinline__ void prefetchL1(const void* p) {
    asm volatile("prefetch.global.L1 [%0];" :: "l"(p));
}
// pack two fp32 into half2 (RN); also return exact fp32 sum of rounded pair
__device__ __forceinline__ uint32_t pack_rn(float a, float b, float& sum) {
    __half2 t = __floats2half2_rn(a, b);
    float2 f = __half22float2(t);
    sum = f.x + f.y;
    return *reinterpret_cast<uint32_t*>(&t);
}

// ---- kernel 1: h = x @ W (64 rows/CTA, 4x4 blocking), scalars + fp16 table + Tmax ----
__global__ void k_gemm_h(const float* __restrict__ x, const float* __restrict__ W,
                         const float* __restrict__ a) {
    __shared__ float sW[FI*FO];       // 32KB; reused as sh[64][65]
    __shared__ float sx[64][132];     // padded: kills bank conflicts
    int tid = threadIdx.x;
    for (int i = tid; i < FI*FO; i += 256) sW[i] = W[i];
    int r0 = blockIdx.x * 64;
    for (int i = tid; i < 64*FI; i += 256)
        sx[i >> 7][i & 127] = x[(size_t)(r0 + (i >> 7))*FI + (i & 127)];
    __syncthreads();
    int c4 = (tid & 15) * 4;
    int r4 = (tid >> 4) * 4;
    float acc4[4][4];
    #pragma unroll
    for (int i = 0; i < 4; i++)
        #pragma unroll
        for (int j = 0; j < 4; j++) acc4[i][j] = 0.f;
    #pragma unroll 4
    for (int k = 0; k < FI; k += 4) {
        float4 xv[4], wv[4];
        #pragma unroll
        for (int i = 0; i < 4; i++) xv[i] = *(const float4*)&sx[r4 + i][k];
        #pragma unroll
        for (int j = 0; j < 4; j++) wv[j] = *(const float4*)&sW[(k + j)*FO + c4];
        #pragma unroll
        for (int i = 0; i < 4; i++) {
            acc4[i][0] += xv[i].x*wv[0].x + xv[i].y*wv[1].x + xv[i].z*wv[2].x + xv[i].w*wv[3].x;
            acc4[i][1] += xv[i].x*wv[0].y + xv[i].y*wv[1].y + xv[i].z*wv[2].y + xv[i].w*wv[3].y;
            acc4[i][2] += xv[i].x*wv[0].z + xv[i].y*wv[1].z + xv[i].z*wv[2].z + xv[i].w*wv[3].z;
            acc4[i][3] += xv[i].x*wv[0].w + xv[i].y*wv[1].w + xv[i].z*wv[2].w + xv[i].w*wv[3].w;
        }
    }
    __syncthreads();    // all sW reads done; reuse as padded sh[64][65]
    float* sh = sW;
    #pragma unroll
    for (int i = 0; i < 4; i++)
        #pragma unroll
        for (int j = 0; j < 4; j++)
            sh[(r4 + i)*65 + c4 + j] = acc4[i][j];
    __syncthreads();
    int w = tid >> 5, lane = tid & 31;
    float tmax = -1e30f;
    for (int rr = w * 8; rr < w * 8 + 8; rr++) {
        float h0 = sh[rr*65 + lane];
        float h1 = sh[rr*65 + 32 + lane];
        float s = h0 * a[lane]      + h1 * a[lane + 32];
        float t = h0 * a[lane + 64] + h1 * a[lane + 96];
        #pragma unroll
        for (int o = 16; o; o >>= 1) {
            s += __shfl_xor_sync(0xffffffffu, s, o);
            t += __shfl_xor_sync(0xffffffffu, t, o);
        }
        tmax = fmaxf(tmax, t);
        if (lane == 0) {
            int gi = r0 + rr;
            g_s[gi] = s; g_t[gi] = t;
            g_u[gi] = expf(t); g_v[gi] = expf(LRALPHA * t);
        }
    }
    if (lane == 0) atomicMax(&g_Tkey, fkey(tmax));
    // N-major fp16 RN table for this 64-row j-slice
    {
        int jj = tid & 63;
        for (int n = tid >> 6; n < FO; n += 4)
            g_Bh[(size_t)n*NN + r0 + jj] = __float2half_rn(sh[jj*65 + n]);
    }
}

// ---------------- kernel 2: single-stream pipelined fp16 HMMA masked GEMM ----------------
// SMEM: s/p/q 2K | W 2 stages x 16K | B 2 stages x 8K = 51200
#define SM_SS    0
#define SM_W     2048
#define A_BYTES  (MT*128)                    // 16384
#define W_STG    A_BYTES
#define SM_B     (SM_W + 2*W_STG)            // 34816
#define B_BYTES  (NBF*128)                   // 8192
#define BSTG     B_BYTES
#define SM_TOTAL (SM_B + 2*BSTG)             // 51200

__global__ void __launch_bounds__(256, 2) k_main_tc(const int* __restrict__ adj) {
    extern __shared__ char smem[];
    uint32_t sb = smem_u32(smem);
    int tid = threadIdx.x, w = tid >> 5, lane = tid & 31;
    int wm = w & 3, wn = w >> 2;                 // 4 M-groups x 2 N-groups
    int i0 = blockIdx.x * MT;
    int sp = blockIdx.y;
    int jbase = sp * (NN / KSPLIT);
    const int nTiles = (NN / KSPLIT) / KT;       // 32

    float* s_s = (float*)(smem + SM_SS);         // [128]
    float* s_p = s_s + 128;
    float* s_q = s_s + 256;
    if (tid < MT) {
        float s = g_s[i0 + tid];
        float T = funkey(g_Tkey);
        float e = s + T;
        float mi = e > 0.f ? e : LRALPHA * e;    // = max_j leakyrelu(s+t_j)
        s_s[tid] = s;
        s_p[tid] = expf(s - mi);
        s_q[tid] = expf(LRALPHA * s - mi);
    }

    float acc[2][4][4];
    #pragma unroll
    for (int mt = 0; mt < 2; mt++)
        #pragma unroll
        for (int nb = 0; nb < 4; nb++)
            #pragma unroll
            for (int e = 0; e < 4; e++) acc[mt][nb][e] = 0.f;
    float rsum[4] = {0.f, 0.f, 0.f, 0.f};

    int nbBase = wn * 4;
    uint32_t aRowByte = (uint32_t)(wm * 32 + (lane & 15)) * 128;
    uint32_t aKHalf   = ((lane >> 4) & 1) * 16;
    uint32_t bByte    = (uint32_t)(lane & 7) * 128 + ((lane >> 3) & 1) * 16
                      + ((lane >> 4) & 1) * 1024;

    // build-phase fixed coordinates
    int seg   = tid & 7;          // j segment of 8
    int rbase = tid >> 3;         // 0..31; row = it*32 + rbase

    auto prefetchB = [&](int tt, int st) {
        int j0 = jbase + tt * KT;
        uint32_t bdst = sb + SM_B + st * BSTG;
        for (int v = tid; v < NBF * 8; v += 256) {
            int n = v >> 3, ch = v & 7;
            cp16(bdst + SWZ((uint32_t)(n * 128 + ch * 16)),
                 g_Bh + (size_t)n * NN + j0 + ch * 8);
        }
    };

    prefetchB(0, 0);
    CP_COMMIT();
    __syncthreads();           // s_s/p/q visible

    // hoist tile-invariant row constants into registers (4 rows per thread)
    float rs[4], rp[4], rq[4];
    #pragma unroll
    for (int it = 0; it < 4; it++) {
        int r = it * 32 + rbase;
        rs[it] = s_s[r]; rp[it] = s_p[r]; rq[it] = s_q[r];
    }

    // build W(tt) fp16-RN tile into stage st; rsum over the ROUNDED values
    auto buildW = [&](int tt, int st) {
        int jc = jbase + tt * KT + seg * 8;
        char* wb = smem + SM_W + st * W_STG;
        float4 t0 = *(const float4*)(g_t + jc);
        float4 t1 = *(const float4*)(g_t + jc + 4);
        float4 u0 = *(const float4*)(g_u + jc);
        float4 u1 = *(const float4*)(g_u + jc + 4);
        float4 v0 = *(const float4*)(g_v + jc);
        float4 v1 = *(const float4*)(g_v + jc + 4);
        #pragma unroll
        for (int it = 0; it < 4; it++) {
            int r = it * 32 + rbase;
            const int* ap = adj + (size_t)(i0 + r) * NN + jc;
            int4 a0 = __ldg((const int4*)ap);
            int4 a1 = __ldg((const int4*)(ap + 4));
            float sr = rs[it], pr_ = rp[it], qr_ = rq[it];
            float w0 = (a0.x > 0) ? ((sr + t0.x > 0.f) ? pr_ * u0.x : qr_ * v0.x) : 0.f;
            float w1 = (a0.y > 0) ? ((sr + t0.y > 0.f) ? pr_ * u0.y : qr_ * v0.y) : 0.f;
            float w2 = (a0.z > 0) ? ((sr + t0.z > 0.f) ? pr_ * u0.z : qr_ * v0.z) : 0.f;
            float w3 = (a0.w > 0) ? ((sr + t0.w > 0.f) ? pr_ * u0.w : qr_ * v0.w) : 0.f;
            float w4 = (a1.x > 0) ? ((sr + t1.x > 0.f) ? pr_ * u1.x : qr_ * v1.x) : 0.f;
            float w5 = (a1.y > 0) ? ((sr + t1.y > 0.f) ? pr_ * u1.y : qr_ * v1.y) : 0.f;
            float w6 = (a1.z > 0) ? ((sr + t1.z > 0.f) ? pr_ * u1.z : qr_ * v1.z) : 0.f;
            float w7 = (a1.w > 0) ? ((sr + t1.w > 0.f) ? pr_ * u1.w : qr_ * v1.w) : 0.f;
            uint4 H;
            float s0, s1, s2, s3;
            H.x = pack_rn(w0, w1, s0);
            H.y = pack_rn(w2, w3, s1);
            H.z = pack_rn(w4, w5, s2);
            H.w = pack_rn(w6, w7, s3);
            rsum[it] += (s0 + s1) + (s2 + s3);
            *(uint4*)(wb + SWZ((uint32_t)(r * 128 + seg * 16))) = H;
        }
    };

    buildW(0, 0);
    __syncthreads();           // W(0) visible to all warps

    for (int t = 0; t < nTiles; t++) {
        int st = t & 1;

        if (t + 1 < nTiles) {
            prefetchB(t + 1, 1 - st);
            CP_COMMIT();
            buildW(t + 1, 1 - st);
            CP_WAIT(1);        // B(t) complete (B(t+1) still in flight)
        } else {
            CP_WAIT(0);
        }

        if (t + 2 < nTiles)
            prefetchL1(adj + (size_t)(i0 + (tid >> 1)) * NN
                       + (jbase + (t + 2) * KT) + (tid & 1) * 32);

        // ---- MMA(t): 4 ksteps, B fragments double-buffered ----
        uint32_t wbase = sb + SM_W + st * W_STG;
        uint32_t bbase = sb + SM_B + st * BSTG;
        uint32_t bhB[2][2][4];
        #pragma unroll
        for (int pr = 0; pr < 2; pr++)
            ldm_x4(bbase + SWZ(bByte + (nbBase + 2 * pr) * 1024u), bhB[0][pr]);
        #pragma unroll
        for (int ks = 0; ks < 4; ks++) {
            const int cb = ks & 1;
            uint32_t kB = (uint32_t)ks * 32;
            uint32_t aH[2][4];
            #pragma unroll
            for (int mt = 0; mt < 2; mt++)
                ldm_x4(wbase + SWZ(aRowByte + mt * 2048u + kB + aKHalf), aH[mt]);
            if (ks < 3) {
                uint32_t kBn = kB + 32;
                #pragma unroll
                for (int pr = 0; pr < 2; pr++)
                    ldm_x4(bbase + SWZ(bByte + (nbBase + 2 * pr) * 1024u + kBn),
                           bhB[cb ^ 1][pr]);
            }
            #pragma unroll
            for (int pr = 0; pr < 2; pr++) {
                mma16816(acc[0][2*pr],   aH[0], bhB[cb][pr]);
                mma16816(acc[1][2*pr],   aH[1], bhB[cb][pr]);
                mma16816(acc[0][2*pr+1], aH[0], bhB[cb][pr] + 2);
                mma16816(acc[1][2*pr+1], aH[1], bhB[cb][pr] + 2);
            }
        }
        __syncthreads();       // all warps done reading W(st), B(st)
    }

    // ---- epilogue: fp32 partials; den via deferred 8-lane reduction ----
    #pragma unroll
    for (int it = 0; it < 4; it++) {
        float rv = rsum[it];
        rv += __shfl_xor_sync(0xffffffffu, rv, 1);
        rv += __shfl_xor_sync(0xffffffffu, rv, 2);
        rv += __shfl_xor_sync(0xffffffffu, rv, 4);
        if (seg == 0)
            g_num[sp][(size_t)(i0 + it * 32 + rbase) * STRIDE_OUT + 64] = rv;
    }
    int gp = lane >> 2, tg = lane & 3;
    #pragma unroll
    for (int mt = 0; mt < 2; mt++) {
        int row0 = i0 + wm * 32 + mt * 16 + gp;
        #pragma unroll
        for (int nb = 0; nb < 4; nb++) {
            int col = (nbBase + nb) * 8 + tg * 2;
            size_t o0 = (size_t)row0 * STRIDE_OUT + col;
            size_t o1 = (size_t)(row0 + 8) * STRIDE_OUT + col;
            g_num[sp][o0]     = acc[mt][nb][0];
            g_num[sp][o0 + 1] = acc[mt][nb][1];
            g_num[sp][o1]     = acc[mt][nb][2];
            g_num[sp][o1 + 1] = acc[mt][nb][3];
        }
    }
}

// ---------------- kernel 3: combine splits, divide, ELU ----------------
__global__ void k_final(float* __restrict__ out) {
    int idx = blockIdx.x * 256 + threadIdx.x;
    int i = idx >> 6, c = idx & 63;
    size_t b = (size_t)i * STRIDE_OUT;
    float num = 0.f, den = 0.f;
    #pragma unroll
    for (int s2 = 0; s2 < KSPLIT; s2++) {
        num += g_num[s2][b + c];
        den += g_num[s2][b + 64];
    }
    float hv = num / den;
    out[idx] = hv > 0.f ? hv : expm1f(hv);
}

extern "C" void kernel_launch(void* const* d_in, const int* in_sizes, int n_in,
                              void* d_out, int out_size) {
    const float* x   = (const float*)d_in[0];
    const int*   adj = (const int*)  d_in[1];
    const float* W   = (const float*)d_in[2];
    const float* a   = (const float*)d_in[3];
    float* out = (float*)d_out;

    cudaFuncSetAttribute(k_main_tc, cudaFuncAttributeMaxDynamicSharedMemorySize, SM_TOTAL);

    k_gemm_h<<<NN/64, 256>>>(x, W, a);
    dim3 gm(NN/MT, KSPLIT);
    k_main_tc<<<gm, 256, SM_TOTAL>>>(adj);
    k_final<<<(NN*FO)/256, 256>>>(out);
}